// round 15
// baseline (speedup 1.0000x reference)
#include <cuda_runtime.h>
#include <cuda_bf16.h>
#include <math.h>

#define NSEQ 3136
#define CD   768
#define NH   12
#define HD   64
#define HID  3072
#define C3   2304

// rounded-weight scratch offsets (bf16 elements)
#define WQKV_OFF 0
#define WPROJ_OFF 1769472               // 2304*768
#define W1_OFF   (WPROJ_OFF + 589824)   // +768*768
#define W2_OFF   (W1_OFF + 2359296)     // +3072*768
#define W_TOTAL  (W2_OFF + 2359296)

// float4-chunk counts per region
#define NC_QKV  (C3 * CD / 4)
#define NC_PROJ (CD * CD / 4)
#define NC_W1   (HID * CD / 4)
#define NC_W2   (CD * HID / 4)
#define NC_ALL  (NC_QKV + NC_PROJ + NC_W1 + NC_W2)

// ---------------- scratch (static device globals; no allocation) -------------
__device__ __nv_bfloat16 g_xn[NSEQ * CD];
__device__ __nv_bfloat16 g_qkv[NSEQ * C3];
__device__ __nv_bfloat16 g_vt[CD * NSEQ];        // V transposed: [dim][token]
__device__ __nv_bfloat16 g_attout[NSEQ * CD];
__device__ __nv_bfloat16 g_h0[NSEQ * CD];
__device__ __nv_bfloat16 g_h1[NSEQ * HID];
__device__ __nv_bfloat16 g_w[W_TOTAL];
__device__ float g_x2[NSEQ * CD];
__device__ float g_maskf[NSEQ];

// ---------------- helpers ----------------------------------------------------
__device__ __forceinline__ float warpSum(float v) {
#pragma unroll
    for (int o = 16; o; o >>= 1) v += __shfl_xor_sync(0xffffffffu, v, o);
    return v;
}
__device__ __forceinline__ unsigned packbf(float lo, float hi) {
    unsigned r;
    asm("cvt.rn.bf16x2.f32 %0, %1, %2;" : "=r"(r) : "f"(hi), "f"(lo));
    return r;
}
__device__ __forceinline__ void cp16(void* s, const void* g) {
    unsigned a = (unsigned)__cvta_generic_to_shared(s);
    asm volatile("cp.async.ca.shared.global [%0], [%1], 16;" :: "r"(a), "l"(g));
}
__device__ __forceinline__ unsigned s2u(const void* p) {
    return (unsigned)__cvta_generic_to_shared(p);
}
__device__ __forceinline__ void ldsm4(unsigned& r0, unsigned& r1, unsigned& r2, unsigned& r3,
                                      unsigned addr) {
    asm volatile("ldmatrix.sync.aligned.m8n8.x4.shared.b16 {%0,%1,%2,%3}, [%4];"
        : "=r"(r0), "=r"(r1), "=r"(r2), "=r"(r3) : "r"(addr));
}
__device__ __forceinline__ void mma_bf16(float* c, const unsigned* a, unsigned b0, unsigned b1) {
    asm volatile(
        "mma.sync.aligned.m16n8k16.row.col.f32.bf16.bf16.f32 "
        "{%0,%1,%2,%3}, {%4,%5,%6,%7}, {%8,%9}, {%0,%1,%2,%3};"
        : "+f"(c[0]), "+f"(c[1]), "+f"(c[2]), "+f"(c[3])
        : "r"(a[0]), "r"(a[1]), "r"(a[2]), "r"(a[3]), "r"(b0), "r"(b1));
}

// ---------------- fused weight conversion (ONE launch) --------------------------
__global__ void __launch_bounds__(256) round_copy_all_kernel(
    const float* __restrict__ qkv_w, const float* __restrict__ proj_w,
    const float* __restrict__ w1, const float* __restrict__ w2,
    unsigned* __restrict__ out)
{
    int i = blockIdx.x * 256 + threadIdx.x;
    if (i >= NC_ALL) return;
    const float* src;
    int off;
    if (i < NC_QKV)                       { src = qkv_w;  off = i; }
    else if (i < NC_QKV + NC_PROJ)        { src = proj_w; off = i - NC_QKV; }
    else if (i < NC_QKV + NC_PROJ + NC_W1){ src = w1;     off = i - NC_QKV - NC_PROJ; }
    else                                  { src = w2;     off = i - NC_QKV - NC_PROJ - NC_W1; }
    float4 v = ((const float4*)src)[off];
    uint2 o;
    o.x = packbf(v.x, v.y);
    o.y = packbf(v.z, v.w);
    ((uint2*)out)[i] = o;
}

// ---------------- fused mask detect + prep --------------------------------------
__global__ void __launch_bounds__(256) mask_fused_kernel(
    const void* __restrict__ mask, float* __restrict__ mf)
{
    __shared__ int flag;
    if (threadIdx.x == 0) flag = 0;
    __syncthreads();
    const unsigned* m32 = (const unsigned*)mask;
    for (int i = threadIdx.x; i < NSEQ / 4; i += 256)
        if (m32[i] > 1u) flag = 1;
    __syncthreads();
    int byteMode = flag;
    int i = blockIdx.x * 256 + threadIdx.x;
    if (i < NSEQ) {
        bool m = byteMode ? (((const unsigned char*)mask)[i] != 0)
                          : (((const int*)mask)[i] != 0);
        mf[i] = m ? -1e30f : 0.f;
    }
}

// ---------------- layernorm (bf16 output) --------------------------------------
__global__ void __launch_bounds__(256) ln_kernel(
    const float* __restrict__ x, const float* __restrict__ sc,
    const float* __restrict__ bi, __nv_bfloat16* __restrict__ y)
{
    int row = blockIdx.x;
    const float* xr = x + (long)row * CD;
    __nv_bfloat16* yr = y + (long)row * CD;
    int t = threadIdx.x;
    float v[3];
    float s = 0.f, s2 = 0.f;
#pragma unroll
    for (int i = 0; i < 3; i++) {
        float a = xr[t + i * 256];
        v[i] = a; s += a; s2 += a * a;
    }
    __shared__ float sh[32], sh2[32];
    float ws = warpSum(s), ws2 = warpSum(s2);
    int lane = t & 31, wid = t >> 5;
    if (lane == 0) { sh[wid] = ws; sh2[wid] = ws2; }
    __syncthreads();
    if (wid == 0) {
        float a = lane < 8 ? sh[lane] : 0.f;
        float b = lane < 8 ? sh2[lane] : 0.f;
        a = warpSum(a); b = warpSum(b);
        if (lane == 0) { sh[0] = a; sh2[0] = b; }
    }
    __syncthreads();
    float mu  = sh[0] * (1.f / CD);
    float var = sh2[0] * (1.f / CD) - mu * mu;
    float inv = rsqrtf(var + 1e-5f);
#pragma unroll
    for (int i = 0; i < 3; i++) {
        int c = t + i * 256;
        yr[c] = __float2bfloat16_rn((v[i] - mu) * inv * sc[c] + bi[c]);
    }
}

// ---------------- flash attention (bf16 + ldmatrix, 3-stage pipeline) ----------
// One block = one (q-tile of 128, head). 4 warps, warp owns 32 q-rows (mi=2).
// K tiles [key][dim], V pre-transposed [dim][token]. 3-deep cp.async K/V ring:
// data consumed at iter j was issued at j-2 -> wait_group 1 nearly free.
// 3 blocks/SM (218KB smem) -> 300 blocks in ONE wave.
#define FLASH_SMEM ((3*64*72 + 3*64*72 + 4*32*72) * 2 + 3*64*4)   // 74496 B

__global__ void __launch_bounds__(128, 3) flash_kernel(
    const __nv_bfloat16* __restrict__ qkv, const __nv_bfloat16* __restrict__ vt,
    const float* __restrict__ maskf, __nv_bfloat16* __restrict__ attout)
{
    extern __shared__ __align__(16) char smc[];
    __nv_bfloat16* Ks = (__nv_bfloat16*)smc;        // 3 * 64*72
    __nv_bfloat16* Vs = Ks + 3 * 64 * 72;           // 3 * 64*72 (rows = dims)
    __nv_bfloat16* Ps = Vs + 3 * 64 * 72;           // 4 warps * 32*72
    float* Ms = (float*)(Ps + 4 * 32 * 72);         // 3 * 64

    int h  = blockIdx.y;
    int m0 = blockIdx.x * 128;
    int tid = threadIdx.x, wid = tid >> 5, lane = tid & 31;
    int g = lane >> 2, t = lane & 3;
    int rowA = lane & 15, hiA = lane >> 4;
    int rowB = (lane & 7) + (lane >> 4) * 8;
    int hiB  = (lane >> 3) & 1;

    const __nv_bfloat16* Qp  = qkv + h * HD;
    const __nv_bfloat16* Kp  = qkv + CD + h * HD;
    const __nv_bfloat16* Vtp = vt + (long)h * HD * NSEQ;

    unsigned qf[4][2][4];
#pragma unroll
    for (int mi = 0; mi < 2; mi++) {
        int r0 = m0 + wid * 32 + mi * 16 + g; if (r0 >= NSEQ) r0 = NSEQ - 1;
        int r1 = r0 + 8;                      if (r1 >= NSEQ) r1 = NSEQ - 1;
        const __nv_bfloat16* q0 = Qp + (long)r0 * C3;
        const __nv_bfloat16* q1 = Qp + (long)r1 * C3;
#pragma unroll
        for (int kb = 0; kb < 4; kb++) {
            qf[kb][mi][0] = *(const unsigned*)&q0[kb * 16 + 2 * t];
            qf[kb][mi][1] = *(const unsigned*)&q1[kb * 16 + 2 * t];
            qf[kb][mi][2] = *(const unsigned*)&q0[kb * 16 + 8 + 2 * t];
            qf[kb][mi][3] = *(const unsigned*)&q1[kb * 16 + 8 + 2 * t];
        }
    }

    float o[2][8][4];
#pragma unroll
    for (int mi = 0; mi < 2; mi++)
#pragma unroll
        for (int ni = 0; ni < 8; ni++)
#pragma unroll
            for (int e = 0; e < 4; e++) o[mi][ni][e] = 0.f;
    float mr[2][2], lr[2][2];
#pragma unroll
    for (int mi = 0; mi < 2; mi++) {
        mr[mi][0] = mr[mi][1] = -3.4e38f;
        lr[mi][0] = lr[mi][1] = 0.f;
    }

    auto loadKV = [&](int buf, int j0) {
#pragma unroll
        for (int i = 0; i < 4; i++) {
            int idx = tid + i * 128;
            int r = idx >> 3, c = (idx & 7) * 8;
            cp16(&Ks[buf * 64 * 72 + r * 72 + c], &Kp[(long)(j0 + r) * C3 + c]);
            cp16(&Vs[buf * 64 * 72 + r * 72 + c], &Vtp[(long)r * NSEQ + j0 + c]);
        }
        if (tid < 16) cp16(&Ms[buf * 64 + tid * 4], &maskf[j0 + tid * 4]);
    };

    const int NJ = NSEQ / 64;   // 49
    loadKV(0, 0);
    asm volatile("cp.async.commit_group;");
    loadKV(1, 64);
    asm volatile("cp.async.commit_group;");

    unsigned* pw = (unsigned*)(Ps + wid * 32 * 72);
    unsigned pwb = s2u(Ps) + wid * 32 * 72 * 2;

    int cur = 0;
    for (int j = 0; j < NJ; j++) {
        if (j + 1 < NJ) asm volatile("cp.async.wait_group 1;");
        else            asm volatile("cp.async.wait_group 0;");
        __syncthreads();      // data for j ready; all warps done with buf (j+2)%3
        if (j + 2 < NJ) {
            int nb = cur + 2; if (nb >= 3) nb -= 3;
            loadKV(nb, (j + 2) * 64);
            asm volatile("cp.async.commit_group;");
        }

        unsigned ksb = s2u(Ks + cur * 64 * 72);
        unsigned vsb = s2u(Vs + cur * 64 * 72);
        const float* ms = Ms + cur * 64;

#pragma unroll
        for (int mi = 0; mi < 2; mi++) {
            float s[8][4];
#pragma unroll
            for (int ni = 0; ni < 8; ni++)
                s[ni][0] = s[ni][1] = s[ni][2] = s[ni][3] = 0.f;
#pragma unroll
            for (int kb = 0; kb < 4; kb++) {
#pragma unroll
                for (int np = 0; np < 8; np += 2) {
                    unsigned b00, b01, b10, b11;
                    ldsm4(b00, b01, b10, b11,
                          ksb + (unsigned)(((np * 8 + rowB) * 36 + kb * 8 + hiB * 4) * 4));
                    mma_bf16(s[np],     qf[kb][mi], b00, b01);
                    mma_bf16(s[np + 1], qf[kb][mi], b10, b11);
                }
            }

            float rm0 = -3.4e38f, rm1 = -3.4e38f;
#pragma unroll
            for (int ni = 0; ni < 8; ni++) {
                int c0 = ni * 8 + 2 * t;
                float a0 = ms[c0], a1 = ms[c0 + 1];
                s[ni][0] = s[ni][0] * 0.125f + a0;
                s[ni][1] = s[ni][1] * 0.125f + a1;
                s[ni][2] = s[ni][2] * 0.125f + a0;
                s[ni][3] = s[ni][3] * 0.125f + a1;
                rm0 = fmaxf(rm0, fmaxf(s[ni][0], s[ni][1]));
                rm1 = fmaxf(rm1, fmaxf(s[ni][2], s[ni][3]));
            }
            rm0 = fmaxf(rm0, __shfl_xor_sync(0xffffffffu, rm0, 1));
            rm0 = fmaxf(rm0, __shfl_xor_sync(0xffffffffu, rm0, 2));
            rm1 = fmaxf(rm1, __shfl_xor_sync(0xffffffffu, rm1, 1));
            rm1 = fmaxf(rm1, __shfl_xor_sync(0xffffffffu, rm1, 2));
            float mn0 = fmaxf(mr[mi][0], rm0), mn1 = fmaxf(mr[mi][1], rm1);
            float f0 = __expf(mr[mi][0] - mn0), f1 = __expf(mr[mi][1] - mn1);
            mr[mi][0] = mn0; mr[mi][1] = mn1;

            float rs0 = 0.f, rs1 = 0.f;
#pragma unroll
            for (int ni = 0; ni < 8; ni++) {
                float p00 = __expf(s[ni][0] - mn0), p01 = __expf(s[ni][1] - mn0);
                float p10 = __expf(s[ni][2] - mn1), p11 = __expf(s[ni][3] - mn1);
                rs0 += p00 + p01; rs1 += p10 + p11;
                pw[(mi * 16 + g) * 36 + ni * 4 + t]     = packbf(p00, p01);
                pw[(mi * 16 + g + 8) * 36 + ni * 4 + t] = packbf(p10, p11);
            }
            rs0 += __shfl_xor_sync(0xffffffffu, rs0, 1);
            rs0 += __shfl_xor_sync(0xffffffffu, rs0, 2);
            rs1 += __shfl_xor_sync(0xffffffffu, rs1, 1);
            rs1 += __shfl_xor_sync(0xffffffffu, rs1, 2);
            lr[mi][0] = lr[mi][0] * f0 + rs0;
            lr[mi][1] = lr[mi][1] * f1 + rs1;

#pragma unroll
            for (int ni = 0; ni < 8; ni++) {
                o[mi][ni][0] *= f0; o[mi][ni][1] *= f0;
                o[mi][ni][2] *= f1; o[mi][ni][3] *= f1;
            }
        }
        __syncwarp();

#pragma unroll
        for (int kb = 0; kb < 4; kb++) {
            unsigned paf0[4], paf1[4];
            ldsm4(paf0[0], paf0[1], paf0[2], paf0[3],
                  pwb + (unsigned)((rowA * 36 + kb * 8 + hiA * 4) * 4));
            ldsm4(paf1[0], paf1[1], paf1[2], paf1[3],
                  pwb + (unsigned)(((16 + rowA) * 36 + kb * 8 + hiA * 4) * 4));
#pragma unroll
            for (int np = 0; np < 8; np += 2) {
                unsigned b00, b01, b10, b11;
                ldsm4(b00, b01, b10, b11,
                      vsb + (unsigned)(((np * 8 + rowB) * 36 + kb * 8 + hiB * 4) * 4));
                mma_bf16(o[0][np],     paf0, b00, b01);
                mma_bf16(o[0][np + 1], paf0, b10, b11);
                mma_bf16(o[1][np],     paf1, b00, b01);
                mma_bf16(o[1][np + 1], paf1, b10, b11);
            }
        }
        cur++; if (cur >= 3) cur = 0;
    }

#pragma unroll
    for (int mi = 0; mi < 2; mi++) {
        float inv0 = 1.f / lr[mi][0], inv1 = 1.f / lr[mi][1];
        int r0 = m0 + wid * 32 + mi * 16 + g, r1 = r0 + 8;
#pragma unroll
        for (int ni = 0; ni < 8; ni++) {
            int col = h * HD + ni * 8 + 2 * t;
            if (r0 < NSEQ)
                *(unsigned*)&attout[(long)r0 * CD + col] =
                    packbf(o[mi][ni][0] * inv0, o[mi][ni][1] * inv0);
            if (r1 < NSEQ)
                *(unsigned*)&attout[(long)r1 * CD + col] =
                    packbf(o[mi][ni][2] * inv1, o[mi][ni][3] * inv1);
        }
    }
}

// ---------------- bf16 mma GEMM, 3-stage pipeline, fused epilogues --------------
// C[M,N] = A[M,K] @ B[N,K]^T. BK=32 (two k16 steps). Warp tile 64x32, ldmatrix.
// BM=64: 4 warps (1x4), 128 thr, 3-stage smem ring (45KB), 4 blk/SM -> 592 slots.
enum { EPI_QKV = 2, EPI_GELU = 4, EPI_RES = 5 };

template<int EPI, int BM>
__global__ void __launch_bounds__(BM * 2, 256 / (BM / 64) / 64) mmgemm(
    const __nv_bfloat16* __restrict__ A, const __nv_bfloat16* __restrict__ B,
    void* __restrict__ Cout,
    int M, int N, int K, int lda, int ldb, int ldc,
    const float* __restrict__ bias, const float* __restrict__ bias2,
    const float* __restrict__ res, const float* __restrict__ gamma,
    __nv_bfloat16* __restrict__ vt)
{
    constexpr int THREADS = BM * 2;
    constexpr int WROWS = BM / 64;
    constexpr int MI = 4, NI = 4;
    constexpr int LDE = 40;            // bf16 elems per smem row (32 + 8 pad) = 80B
    constexpr int LDW = 20;            // words per row

    __shared__ __align__(16) __nv_bfloat16 As[3][BM * LDE];
    __shared__ __align__(16) __nv_bfloat16 Bs[3][128 * LDE];

    int tid  = threadIdx.x;
    int wid  = tid >> 5;
    int lane = tid & 31;
    int g = lane >> 2, t = lane & 3;
    int rowA = lane & 15, hiA = lane >> 4;
    int rowB = (lane & 7) + (lane >> 4) * 8;
    int hiB  = (lane >> 3) & 1;
    int wm = (wid % WROWS) * 64;
    int wn = (wid / WROWS) * 32;
    int m0 = blockIdx.x * BM, n0 = blockIdx.y * 128;

    auto ldA = [&](int buf, int k0) {
#pragma unroll
        for (int i = 0; i < 2; i++) {
            int idx = tid + i * THREADS;
            int r = idx >> 2, c = (idx & 3) * 8;
            int row = m0 + r; if (row >= M) row = M - 1;
            cp16(&As[buf][r * LDE + c], &A[(long)row * lda + k0 + c]);
        }
    };
    auto ldB = [&](int buf, int k0) {
#pragma unroll
        for (int i = 0; i < 256 / BM; i++) {
            int idx = tid + i * THREADS;
            int r = idx >> 2, c = (idx & 3) * 8;
            int row = n0 + r; if (row >= N) row = N - 1;
            cp16(&Bs[buf][r * LDE + c], &B[(long)row * ldb + k0 + c]);
        }
    };

    float acc[MI][NI][4];
#pragma unroll
    for (int mi = 0; mi < MI; mi++)
#pragma unroll
        for (int ni = 0; ni < NI; ni++)
#pragma unroll
            for (int e = 0; e < 4; e++) acc[mi][ni][e] = 0.f;

    int KT = K / 32;
    ldA(0, 0); ldB(0, 0);
    asm volatile("cp.async.commit_group;");
    ldA(1, 32); ldB(1, 32);
    asm volatile("cp.async.commit_group;");

    int cur = 0;
    for (int kt = 0; kt < KT; kt++) {
        if (kt + 1 < KT) asm volatile("cp.async.wait_group 1;");
        else             asm volatile("cp.async.wait_group 0;");
        __syncthreads();      // data for kt ready; all warps done with buf (kt+2)%3
        if (kt + 2 < KT) {
            int nb = cur + 2; if (nb >= 3) nb -= 3;
            ldA(nb, (kt + 2) * 32);
            ldB(nb, (kt + 2) * 32);
            asm volatile("cp.async.commit_group;");
        }

        unsigned asb = s2u(As[cur]);
        unsigned bsb = s2u(Bs[cur]);
#pragma unroll
        for (int kb = 0; kb < 16; kb += 8) {
            unsigned af[MI][4], bf[NI][2];
#pragma unroll
            for (int mi = 0; mi < MI; mi++)
                ldsm4(af[mi][0], af[mi][1], af[mi][2], af[mi][3],
                      asb + (unsigned)(((wm + mi * 16 + rowA) * LDW + kb + hiA * 4) * 4));
#pragma unroll
            for (int np = 0; np < NI; np += 2)
                ldsm4(bf[np][0], bf[np][1], bf[np + 1][0], bf[np + 1][1],
                      bsb + (unsigned)(((wn + np * 8 + rowB) * LDW + kb + hiB * 4) * 4));
#pragma unroll
            for (int mi = 0; mi < MI; mi++)
#pragma unroll
                for (int ni = 0; ni < NI; ni++)
                    mma_bf16(acc[mi][ni], af[mi], bf[ni][0], bf[ni][1]);
        }
        cur++; if (cur >= 3) cur = 0;
    }

#pragma unroll
    for (int mi = 0; mi < MI; mi++) {
#pragma unroll
        for (int ni = 0; ni < NI; ni++) {
            int col = n0 + wn + ni * 8 + 2 * t;
            if (col >= N) continue;
#pragma unroll
            for (int half = 0; half < 2; half++) {
                int row = m0 + wm + mi * 16 + g + half * 8;
                if (row >= M) continue;
                float v0 = acc[mi][ni][half * 2 + 0];
                float v1 = acc[mi][ni][half * 2 + 1];
                if (EPI == EPI_QKV) {
                    float b0 = (col < CD) ? bias[col]
                             : (col < 2 * CD) ? 0.f : bias2[col - 2 * CD];
                    int c1 = col + 1;
                    float b1 = (c1 < CD) ? bias[c1]
                             : (c1 < 2 * CD) ? 0.f : bias2[c1 - 2 * CD];
                    v0 += b0; v1 += b1;
                    if (col < 2 * CD) {
                        __nv_bfloat16* q = (__nv_bfloat16*)Cout;
                        *(unsigned*)&q[(long)row * ldc + col] = packbf(v0, v1);
                    } else {
                        int d = col - 2 * CD;
                        vt[(long)d * NSEQ + row]       = __float2bfloat16_rn(v0);
                        vt[(long)(d + 1) * NSEQ + row] = __float2bfloat16_rn(v1);
                    }
                } else if (EPI == EPI_GELU) {
                    v0 += bias[col]; v1 += bias[col + 1];
                    v0 = 0.5f * v0 * (1.f + erff(v0 * 0.70710678118654752f));
                    v1 = 0.5f * v1 * (1.f + erff(v1 * 0.70710678118654752f));
                    __nv_bfloat16* q = (__nv_bfloat16*)Cout;
                    *(unsigned*)&q[(long)row * ldc + col] = packbf(v0, v1);
                } else {  // EPI_RES
                    const float* rr = &res[(long)row * ldc + col];
                    float* q = (float*)Cout;
                    float2 ov;
                    ov.x = rr[0] + gamma[col]     * (v0 + bias[col]);
                    ov.y = rr[1] + gamma[col + 1] * (v1 + bias[col + 1]);
                    *(float2*)&q[(long)row * ldc + col] = ov;
                }
            }
        }
    }
}

// ---------------- launch -------------------------------------------------------
extern "C" void kernel_launch(void* const* d_in, const int* in_sizes, int n_in,
                              void* d_out, int out_size)
{
    const float* x      = (const float*)d_in[0];
    const void*  mask   = d_in[1];
    const float* qkv_w  = (const float*)d_in[2];
    const float* q_bias = (const float*)d_in[3];
    const float* v_bias = (const float*)d_in[4];
    const float* proj_w = (const float*)d_in[5];
    const float* proj_b = (const float*)d_in[6];
    const float* n1s    = (const float*)d_in[7];
    const float* n1b    = (const float*)d_in[8];
    const float* n2s    = (const float*)d_in[9];
    const float* n2b    = (const float*)d_in[10];
    const float* w1     = (const float*)d_in[11];
    const float* b1     = (const float*)d_in[12];
    const float* w2     = (const float*)d_in[13];
    const float* b2     = (const float*)d_in[14];
    const float* g1     = (const float*)d_in[15];
    const float* g2     = (const float*)d_in[16];
    float* out = (float*)d_out;

    __nv_bfloat16 *xn, *qkv, *vt, *attout, *h0, *h1, *w;
    float *x2, *maskf;
    cudaGetSymbolAddress((void**)&xn,     g_xn);
    cudaGetSymbolAddress((void**)&qkv,    g_qkv);
    cudaGetSymbolAddress((void**)&vt,     g_vt);
    cudaGetSymbolAddress((void**)&attout, g_attout);
    cudaGetSymbolAddress((void**)&h0,     g_h0);
    cudaGetSymbolAddress((void**)&h1,     g_h1);
    cudaGetSymbolAddress((void**)&w,      g_w);
    cudaGetSymbolAddress((void**)&x2,     g_x2);
    cudaGetSymbolAddress((void**)&maskf,  g_maskf);

    static int smem_set = 0;
    if (!smem_set) {
        cudaFuncSetAttribute(flash_kernel,
                             cudaFuncAttributeMaxDynamicSharedMemorySize, FLASH_SMEM);
        smem_set = 1;
    }

    // 0. convert all weights to bf16 in ONE launch
    round_copy_all_kernel<<<(NC_ALL + 255) / 256, 256>>>(
        qkv_w, proj_w, w1, w2, (unsigned*)w);

    // 1. LN1 + fused mask prep
    ln_kernel<<<NSEQ, 256>>>(x, n1s, n1b, xn);
    mask_fused_kernel<<<(NSEQ + 255) / 256, 256>>>(mask, maskf);

    // 2. QKV projection (BM=64: 882 tiles over 592 slots)
    mmgemm<EPI_QKV, 64><<<dim3(49, C3 / 128, 1), 128>>>(
        xn, w + WQKV_OFF, qkv, NSEQ, C3, CD, CD, CD, C3,
        q_bias, v_bias, nullptr, nullptr, vt);

    // 3-5. flash attention
    flash_kernel<<<dim3(25, NH), 128, FLASH_SMEM>>>(qkv, vt, maskf, attout);

    // 6. proj + residual (BM=64, 294 tiles, single round)
    mmgemm<EPI_RES, 64><<<dim3(49, CD / 128, 1), 128>>>(
        attout, w + WPROJ_OFF, x2, NSEQ, CD, CD, CD, CD, CD,
        proj_b, nullptr, x, g1, nullptr);

    // 7. LN2
    ln_kernel<<<NSEQ, 256>>>(x2, n2s, n2b, h0);

    // 8. MLP1 + exact GELU (BM=64: 1176 tiles = 1.99 rounds)
    mmgemm<EPI_GELU, 64><<<dim3(49, HID / 128, 1), 128>>>(
        h0, w + W1_OFF, h1, NSEQ, HID, CD, CD, CD, HID,
        b1, nullptr, nullptr, nullptr, nullptr);

    // 9. MLP2 + final residual (BM=64)
    mmgemm<EPI_RES, 64><<<dim3(49, CD / 128, 1), 128>>>(
        h1, w + W2_OFF, out, NSEQ, CD, HID, HID, HID, CD,
        b2, nullptr, x2, g2, nullptr);
}

// round 17
// speedup vs baseline: 1.0303x; 1.0303x over previous
#include <cuda_runtime.h>
#include <cuda_bf16.h>
#include <math.h>

#define NSEQ 3136
#define CD   768
#define NH   12
#define HD   64
#define HID  3072
#define C3   2304

// rounded-weight scratch offsets (bf16 elements)
#define WQKV_OFF 0
#define WPROJ_OFF 1769472               // 2304*768
#define W1_OFF   (WPROJ_OFF + 589824)   // +768*768
#define W2_OFF   (W1_OFF + 2359296)     // +3072*768
#define W_TOTAL  (W2_OFF + 2359296)

// float4-chunk counts per region
#define NC_QKV  (C3 * CD / 4)
#define NC_PROJ (CD * CD / 4)
#define NC_W1   (HID * CD / 4)
#define NC_W2   (CD * HID / 4)
#define NC_ALL  (NC_QKV + NC_PROJ + NC_W1 + NC_W2)

// GEMM: BM=64, BN=128, BK=64. smem rows 72 bf16 = 144B (LDW=36 words).
#define GLDE 72
#define GEMM_SMEM ((2 * 64 * GLDE + 2 * 128 * GLDE) * 2)   // 55296 B

// ---------------- scratch (static device globals; no allocation) -------------
__device__ __nv_bfloat16 g_xn[NSEQ * CD];
__device__ __nv_bfloat16 g_qkv[NSEQ * C3];
__device__ __nv_bfloat16 g_vt[CD * NSEQ];        // V transposed: [dim][token]
__device__ __nv_bfloat16 g_attout[NSEQ * CD];
__device__ __nv_bfloat16 g_h0[NSEQ * CD];
__device__ __nv_bfloat16 g_h1[NSEQ * HID];
__device__ __nv_bfloat16 g_w[W_TOTAL];
__device__ float g_x2[NSEQ * CD];
__device__ float g_maskf[NSEQ];

// ---------------- helpers ----------------------------------------------------
__device__ __forceinline__ float warpSum(float v) {
#pragma unroll
    for (int o = 16; o; o >>= 1) v += __shfl_xor_sync(0xffffffffu, v, o);
    return v;
}
__device__ __forceinline__ unsigned packbf(float lo, float hi) {
    unsigned r;
    asm("cvt.rn.bf16x2.f32 %0, %1, %2;" : "=r"(r) : "f"(hi), "f"(lo));
    return r;
}
__device__ __forceinline__ void cp16(void* s, const void* g) {
    unsigned a = (unsigned)__cvta_generic_to_shared(s);
    asm volatile("cp.async.ca.shared.global [%0], [%1], 16;" :: "r"(a), "l"(g));
}
__device__ __forceinline__ unsigned s2u(const void* p) {
    return (unsigned)__cvta_generic_to_shared(p);
}
__device__ __forceinline__ void ldsm4(unsigned& r0, unsigned& r1, unsigned& r2, unsigned& r3,
                                      unsigned addr) {
    asm volatile("ldmatrix.sync.aligned.m8n8.x4.shared.b16 {%0,%1,%2,%3}, [%4];"
        : "=r"(r0), "=r"(r1), "=r"(r2), "=r"(r3) : "r"(addr));
}
__device__ __forceinline__ void mma_bf16(float* c, const unsigned* a, unsigned b0, unsigned b1) {
    asm volatile(
        "mma.sync.aligned.m16n8k16.row.col.f32.bf16.bf16.f32 "
        "{%0,%1,%2,%3}, {%4,%5,%6,%7}, {%8,%9}, {%0,%1,%2,%3};"
        : "+f"(c[0]), "+f"(c[1]), "+f"(c[2]), "+f"(c[3])
        : "r"(a[0]), "r"(a[1]), "r"(a[2]), "r"(a[3]), "r"(b0), "r"(b1));
}

// ---------------- fused weight conversion (ONE launch) --------------------------
__global__ void __launch_bounds__(256) round_copy_all_kernel(
    const float* __restrict__ qkv_w, const float* __restrict__ proj_w,
    const float* __restrict__ w1, const float* __restrict__ w2,
    unsigned* __restrict__ out)
{
    int i = blockIdx.x * 256 + threadIdx.x;
    if (i >= NC_ALL) return;
    const float* src;
    int off;
    if (i < NC_QKV)                       { src = qkv_w;  off = i; }
    else if (i < NC_QKV + NC_PROJ)        { src = proj_w; off = i - NC_QKV; }
    else if (i < NC_QKV + NC_PROJ + NC_W1){ src = w1;     off = i - NC_QKV - NC_PROJ; }
    else                                  { src = w2;     off = i - NC_QKV - NC_PROJ - NC_W1; }
    float4 v = ((const float4*)src)[off];
    uint2 o;
    o.x = packbf(v.x, v.y);
    o.y = packbf(v.z, v.w);
    ((uint2*)out)[i] = o;
}

// ---------------- fused mask detect + prep --------------------------------------
__global__ void __launch_bounds__(256) mask_fused_kernel(
    const void* __restrict__ mask, float* __restrict__ mf)
{
    __shared__ int flag;
    if (threadIdx.x == 0) flag = 0;
    __syncthreads();
    const unsigned* m32 = (const unsigned*)mask;
    for (int i = threadIdx.x; i < NSEQ / 4; i += 256)
        if (m32[i] > 1u) flag = 1;
    __syncthreads();
    int byteMode = flag;
    int i = blockIdx.x * 256 + threadIdx.x;
    if (i < NSEQ) {
        bool m = byteMode ? (((const unsigned char*)mask)[i] != 0)
                          : (((const int*)mask)[i] != 0);
        mf[i] = m ? -1e30f : 0.f;
    }
}

// ---------------- layernorm (bf16 output) --------------------------------------
__global__ void __launch_bounds__(256) ln_kernel(
    const float* __restrict__ x, const float* __restrict__ sc,
    const float* __restrict__ bi, __nv_bfloat16* __restrict__ y)
{
    int row = blockIdx.x;
    const float* xr = x + (long)row * CD;
    __nv_bfloat16* yr = y + (long)row * CD;
    int t = threadIdx.x;
    float v[3];
    float s = 0.f, s2 = 0.f;
#pragma unroll
    for (int i = 0; i < 3; i++) {
        float a = xr[t + i * 256];
        v[i] = a; s += a; s2 += a * a;
    }
    __shared__ float sh[32], sh2[32];
    float ws = warpSum(s), ws2 = warpSum(s2);
    int lane = t & 31, wid = t >> 5;
    if (lane == 0) { sh[wid] = ws; sh2[wid] = ws2; }
    __syncthreads();
    if (wid == 0) {
        float a = lane < 8 ? sh[lane] : 0.f;
        float b = lane < 8 ? sh2[lane] : 0.f;
        a = warpSum(a); b = warpSum(b);
        if (lane == 0) { sh[0] = a; sh2[0] = b; }
    }
    __syncthreads();
    float mu  = sh[0] * (1.f / CD);
    float var = sh2[0] * (1.f / CD) - mu * mu;
    float inv = rsqrtf(var + 1e-5f);
#pragma unroll
    for (int i = 0; i < 3; i++) {
        int c = t + i * 256;
        yr[c] = __float2bfloat16_rn((v[i] - mu) * inv * sc[c] + bi[c]);
    }
}

// ---------------- flash attention (bf16 + ldmatrix, 3-stage pipeline) ----------
// Kept exactly as R15 (the 3-stage ring measurably helped flash).
#define FLASH_SMEM ((3*64*72 + 3*64*72 + 4*32*72) * 2 + 3*64*4)   // 74496 B

__global__ void __launch_bounds__(128, 3) flash_kernel(
    const __nv_bfloat16* __restrict__ qkv, const __nv_bfloat16* __restrict__ vt,
    const float* __restrict__ maskf, __nv_bfloat16* __restrict__ attout)
{
    extern __shared__ __align__(16) char smc[];
    __nv_bfloat16* Ks = (__nv_bfloat16*)smc;        // 3 * 64*72
    __nv_bfloat16* Vs = Ks + 3 * 64 * 72;           // 3 * 64*72 (rows = dims)
    __nv_bfloat16* Ps = Vs + 3 * 64 * 72;           // 4 warps * 32*72
    float* Ms = (float*)(Ps + 4 * 32 * 72);         // 3 * 64

    int h  = blockIdx.y;
    int m0 = blockIdx.x * 128;
    int tid = threadIdx.x, wid = tid >> 5, lane = tid & 31;
    int g = lane >> 2, t = lane & 3;
    int rowA = lane & 15, hiA = lane >> 4;
    int rowB = (lane & 7) + (lane >> 4) * 8;
    int hiB  = (lane >> 3) & 1;

    const __nv_bfloat16* Qp  = qkv + h * HD;
    const __nv_bfloat16* Kp  = qkv + CD + h * HD;
    const __nv_bfloat16* Vtp = vt + (long)h * HD * NSEQ;

    unsigned qf[4][2][4];
#pragma unroll
    for (int mi = 0; mi < 2; mi++) {
        int r0 = m0 + wid * 32 + mi * 16 + g; if (r0 >= NSEQ) r0 = NSEQ - 1;
        int r1 = r0 + 8;                      if (r1 >= NSEQ) r1 = NSEQ - 1;
        const __nv_bfloat16* q0 = Qp + (long)r0 * C3;
        const __nv_bfloat16* q1 = Qp + (long)r1 * C3;
#pragma unroll
        for (int kb = 0; kb < 4; kb++) {
            qf[kb][mi][0] = *(const unsigned*)&q0[kb * 16 + 2 * t];
            qf[kb][mi][1] = *(const unsigned*)&q1[kb * 16 + 2 * t];
            qf[kb][mi][2] = *(const unsigned*)&q0[kb * 16 + 8 + 2 * t];
            qf[kb][mi][3] = *(const unsigned*)&q1[kb * 16 + 8 + 2 * t];
        }
    }

    float o[2][8][4];
#pragma unroll
    for (int mi = 0; mi < 2; mi++)
#pragma unroll
        for (int ni = 0; ni < 8; ni++)
#pragma unroll
            for (int e = 0; e < 4; e++) o[mi][ni][e] = 0.f;
    float mr[2][2], lr[2][2];
#pragma unroll
    for (int mi = 0; mi < 2; mi++) {
        mr[mi][0] = mr[mi][1] = -3.4e38f;
        lr[mi][0] = lr[mi][1] = 0.f;
    }

    auto loadKV = [&](int buf, int j0) {
#pragma unroll
        for (int i = 0; i < 4; i++) {
            int idx = tid + i * 128;
            int r = idx >> 3, c = (idx & 7) * 8;
            cp16(&Ks[buf * 64 * 72 + r * 72 + c], &Kp[(long)(j0 + r) * C3 + c]);
            cp16(&Vs[buf * 64 * 72 + r * 72 + c], &Vtp[(long)r * NSEQ + j0 + c]);
        }
        if (tid < 16) cp16(&Ms[buf * 64 + tid * 4], &maskf[j0 + tid * 4]);
    };

    const int NJ = NSEQ / 64;   // 49
    loadKV(0, 0);
    asm volatile("cp.async.commit_group;");
    loadKV(1, 64);
    asm volatile("cp.async.commit_group;");

    unsigned* pw = (unsigned*)(Ps + wid * 32 * 72);
    unsigned pwb = s2u(Ps) + wid * 32 * 72 * 2;

    int cur = 0;
    for (int j = 0; j < NJ; j++) {
        if (j + 1 < NJ) asm volatile("cp.async.wait_group 1;");
        else            asm volatile("cp.async.wait_group 0;");
        __syncthreads();
        if (j + 2 < NJ) {
            int nb = cur + 2; if (nb >= 3) nb -= 3;
            loadKV(nb, (j + 2) * 64);
            asm volatile("cp.async.commit_group;");
        }

        unsigned ksb = s2u(Ks + cur * 64 * 72);
        unsigned vsb = s2u(Vs + cur * 64 * 72);
        const float* ms = Ms + cur * 64;

#pragma unroll
        for (int mi = 0; mi < 2; mi++) {
            float s[8][4];
#pragma unroll
            for (int ni = 0; ni < 8; ni++)
                s[ni][0] = s[ni][1] = s[ni][2] = s[ni][3] = 0.f;
#pragma unroll
            for (int kb = 0; kb < 4; kb++) {
#pragma unroll
                for (int np = 0; np < 8; np += 2) {
                    unsigned b00, b01, b10, b11;
                    ldsm4(b00, b01, b10, b11,
                          ksb + (unsigned)(((np * 8 + rowB) * 36 + kb * 8 + hiB * 4) * 4));
                    mma_bf16(s[np],     qf[kb][mi], b00, b01);
                    mma_bf16(s[np + 1], qf[kb][mi], b10, b11);
                }
            }

            float rm0 = -3.4e38f, rm1 = -3.4e38f;
#pragma unroll
            for (int ni = 0; ni < 8; ni++) {
                int c0 = ni * 8 + 2 * t;
                float a0 = ms[c0], a1 = ms[c0 + 1];
                s[ni][0] = s[ni][0] * 0.125f + a0;
                s[ni][1] = s[ni][1] * 0.125f + a1;
                s[ni][2] = s[ni][2] * 0.125f + a0;
                s[ni][3] = s[ni][3] * 0.125f + a1;
                rm0 = fmaxf(rm0, fmaxf(s[ni][0], s[ni][1]));
                rm1 = fmaxf(rm1, fmaxf(s[ni][2], s[ni][3]));
            }
            rm0 = fmaxf(rm0, __shfl_xor_sync(0xffffffffu, rm0, 1));
            rm0 = fmaxf(rm0, __shfl_xor_sync(0xffffffffu, rm0, 2));
            rm1 = fmaxf(rm1, __shfl_xor_sync(0xffffffffu, rm1, 1));
            rm1 = fmaxf(rm1, __shfl_xor_sync(0xffffffffu, rm1, 2));
            float mn0 = fmaxf(mr[mi][0], rm0), mn1 = fmaxf(mr[mi][1], rm1);
            float f0 = __expf(mr[mi][0] - mn0), f1 = __expf(mr[mi][1] - mn1);
            mr[mi][0] = mn0; mr[mi][1] = mn1;

            float rs0 = 0.f, rs1 = 0.f;
#pragma unroll
            for (int ni = 0; ni < 8; ni++) {
                float p00 = __expf(s[ni][0] - mn0), p01 = __expf(s[ni][1] - mn0);
                float p10 = __expf(s[ni][2] - mn1), p11 = __expf(s[ni][3] - mn1);
                rs0 += p00 + p01; rs1 += p10 + p11;
                pw[(mi * 16 + g) * 36 + ni * 4 + t]     = packbf(p00, p01);
                pw[(mi * 16 + g + 8) * 36 + ni * 4 + t] = packbf(p10, p11);
            }
            rs0 += __shfl_xor_sync(0xffffffffu, rs0, 1);
            rs0 += __shfl_xor_sync(0xffffffffu, rs0, 2);
            rs1 += __shfl_xor_sync(0xffffffffu, rs1, 1);
            rs1 += __shfl_xor_sync(0xffffffffu, rs1, 2);
            lr[mi][0] = lr[mi][0] * f0 + rs0;
            lr[mi][1] = lr[mi][1] * f1 + rs1;

#pragma unroll
            for (int ni = 0; ni < 8; ni++) {
                o[mi][ni][0] *= f0; o[mi][ni][1] *= f0;
                o[mi][ni][2] *= f1; o[mi][ni][3] *= f1;
            }
        }
        __syncwarp();

#pragma unroll
        for (int kb = 0; kb < 4; kb++) {
            unsigned paf0[4], paf1[4];
            ldsm4(paf0[0], paf0[1], paf0[2], paf0[3],
                  pwb + (unsigned)((rowA * 36 + kb * 8 + hiA * 4) * 4));
            ldsm4(paf1[0], paf1[1], paf1[2], paf1[3],
                  pwb + (unsigned)(((16 + rowA) * 36 + kb * 8 + hiA * 4) * 4));
#pragma unroll
            for (int np = 0; np < 8; np += 2) {
                unsigned b00, b01, b10, b11;
                ldsm4(b00, b01, b10, b11,
                      vsb + (unsigned)(((np * 8 + rowB) * 36 + kb * 8 + hiB * 4) * 4));
                mma_bf16(o[0][np],     paf0, b00, b01);
                mma_bf16(o[0][np + 1], paf0, b10, b11);
                mma_bf16(o[1][np],     paf1, b00, b01);
                mma_bf16(o[1][np + 1], paf1, b10, b11);
            }
        }
        cur++; if (cur >= 3) cur = 0;
    }

#pragma unroll
    for (int mi = 0; mi < 2; mi++) {
        float inv0 = 1.f / lr[mi][0], inv1 = 1.f / lr[mi][1];
        int r0 = m0 + wid * 32 + mi * 16 + g, r1 = r0 + 8;
#pragma unroll
        for (int ni = 0; ni < 8; ni++) {
            int col = h * HD + ni * 8 + 2 * t;
            if (r0 < NSEQ)
                *(unsigned*)&attout[(long)r0 * CD + col] =
                    packbf(o[mi][ni][0] * inv0, o[mi][ni][1] * inv0);
            if (r1 < NSEQ)
                *(unsigned*)&attout[(long)r1 * CD + col] =
                    packbf(o[mi][ni][2] * inv1, o[mi][ni][3] * inv1);
        }
    }
}

// ---------------- bf16 mma GEMM: 2-stage, BK=64, fused epilogues ----------------
// C[M,N] = A[M,K] @ B[N,K]^T. BK=64 (four k16 steps) halves sync count vs BK=32.
// Warp tile 64x32, ldmatrix, 128 thr, dynamic smem 54KB, 4 blk/SM -> 592 slots.
enum { EPI_QKV = 2, EPI_GELU = 4, EPI_RES = 5 };

template<int EPI>
__global__ void __launch_bounds__(128, 4) mmgemm(
    const __nv_bfloat16* __restrict__ A, const __nv_bfloat16* __restrict__ B,
    void* __restrict__ Cout,
    int M, int N, int K, int lda, int ldb, int ldc,
    const float* __restrict__ bias, const float* __restrict__ bias2,
    const float* __restrict__ res, const float* __restrict__ gamma,
    __nv_bfloat16* __restrict__ vt)
{
    constexpr int MI = 4, NI = 4;
    constexpr int LDW = 36;            // words per smem row (144B)

    extern __shared__ __align__(16) __nv_bfloat16 gsm[];
    __nv_bfloat16* As = gsm;                       // 2 x 64*72
    __nv_bfloat16* Bs = gsm + 2 * 64 * GLDE;       // 2 x 128*72

    int tid  = threadIdx.x;
    int wid  = tid >> 5;
    int lane = tid & 31;
    int g = lane >> 2, t = lane & 3;
    int rowA = lane & 15, hiA = lane >> 4;
    int rowB = (lane & 7) + (lane >> 4) * 8;
    int hiB  = (lane >> 3) & 1;
    int wn = wid * 32;                 // 4 warps across N
    int m0 = blockIdx.x * 64, n0 = blockIdx.y * 128;

    auto ldA = [&](int buf, int k0) {
#pragma unroll
        for (int i = 0; i < 4; i++) {
            int idx = tid + i * 128;           // 512 chunks
            int r = idx >> 3, c = (idx & 7) * 8;
            int row = m0 + r; if (row >= M) row = M - 1;
            cp16(&As[buf * 64 * GLDE + r * GLDE + c], &A[(long)row * lda + k0 + c]);
        }
    };
    auto ldB = [&](int buf, int k0) {
#pragma unroll
        for (int i = 0; i < 8; i++) {
            int idx = tid + i * 128;           // 1024 chunks
            int r = idx >> 3, c = (idx & 7) * 8;
            int row = n0 + r; if (row >= N) row = N - 1;
            cp16(&Bs[buf * 128 * GLDE + r * GLDE + c], &B[(long)row * ldb + k0 + c]);
        }
    };

    float acc[MI][NI][4];
#pragma unroll
    for (int mi = 0; mi < MI; mi++)
#pragma unroll
        for (int ni = 0; ni < NI; ni++)
#pragma unroll
            for (int e = 0; e < 4; e++) acc[mi][ni][e] = 0.f;

    int KT = K / 64;
    ldA(0, 0); ldB(0, 0);
    asm volatile("cp.async.commit_group;");

    for (int kt = 0; kt < KT; kt++) {
        int cur = kt & 1;
        asm volatile("cp.async.wait_group 0;");
        __syncthreads();                       // data ready + prev compute done
        if (kt + 1 < KT) {
            ldA(cur ^ 1, (kt + 1) * 64);
            ldB(cur ^ 1, (kt + 1) * 64);
            asm volatile("cp.async.commit_group;");
        }

        unsigned asb = s2u(As + cur * 64 * GLDE);
        unsigned bsb = s2u(Bs + cur * 128 * GLDE);
#pragma unroll
        for (int kb = 0; kb < 32; kb += 8) {   // four k16 steps (word offs 0,8,16,24)
            unsigned af[MI][4], bf[NI][2];
#pragma unroll
            for (int mi = 0; mi < MI; mi++)
                ldsm4(af[mi][0], af[mi][1], af[mi][2], af[mi][3],
                      asb + (unsigned)(((mi * 16 + rowA) * LDW + kb + hiA * 4) * 4));
#pragma unroll
            for (int np = 0; np < NI; np += 2)
                ldsm4(bf[np][0], bf[np][1], bf[np + 1][0], bf[np + 1][1],
                      bsb + (unsigned)(((wn + np * 8 + rowB) * LDW + kb + hiB * 4) * 4));
#pragma unroll
            for (int mi = 0; mi < MI; mi++)
#pragma unroll
                for (int ni = 0; ni < NI; ni++)
                    mma_bf16(acc[mi][ni], af[mi], bf[ni][0], bf[ni][1]);
        }
        // no bottom sync: next top barrier protects buffers
    }

#pragma unroll
    for (int mi = 0; mi < MI; mi++) {
#pragma unroll
        for (int ni = 0; ni < NI; ni++) {
            int col = n0 + wn + ni * 8 + 2 * t;
            if (col >= N) continue;
#pragma unroll
            for (int half = 0; half < 2; half++) {
                int row = m0 + mi * 16 + g + half * 8;
                if (row >= M) continue;
                float v0 = acc[mi][ni][half * 2 + 0];
                float v1 = acc[mi][ni][half * 2 + 1];
                if (EPI == EPI_QKV) {
                    float b0 = (col < CD) ? bias[col]
                             : (col < 2 * CD) ? 0.f : bias2[col - 2 * CD];
                    int c1 = col + 1;
                    float b1 = (c1 < CD) ? bias[c1]
                             : (c1 < 2 * CD) ? 0.f : bias2[c1 - 2 * CD];
                    v0 += b0; v1 += b1;
                    if (col < 2 * CD) {
                        __nv_bfloat16* q = (__nv_bfloat16*)Cout;
                        *(unsigned*)&q[(long)row * ldc + col] = packbf(v0, v1);
                    } else {
                        int d = col - 2 * CD;
                        vt[(long)d * NSEQ + row]       = __float2bfloat16_rn(v0);
                        vt[(long)(d + 1) * NSEQ + row] = __float2bfloat16_rn(v1);
                    }
                } else if (EPI == EPI_GELU) {
                    v0 += bias[col]; v1 += bias[col + 1];
                    v0 = 0.5f * v0 * (1.f + erff(v0 * 0.70710678118654752f));
                    v1 = 0.5f * v1 * (1.f + erff(v1 * 0.70710678118654752f));
                    __nv_bfloat16* q = (__nv_bfloat16*)Cout;
                    *(unsigned*)&q[(long)row * ldc + col] = packbf(v0, v1);
                } else {  // EPI_RES
                    const float* rr = &res[(long)row * ldc + col];
                    float* q = (float*)Cout;
                    float2 ov;
                    ov.x = rr[0] + gamma[col]     * (v0 + bias[col]);
                    ov.y = rr[1] + gamma[col + 1] * (v1 + bias[col + 1]);
                    *(float2*)&q[(long)row * ldc + col] = ov;
                }
            }
        }
    }
}

// ---------------- launch -------------------------------------------------------
extern "C" void kernel_launch(void* const* d_in, const int* in_sizes, int n_in,
                              void* d_out, int out_size)
{
    const float* x      = (const float*)d_in[0];
    const void*  mask   = d_in[1];
    const float* qkv_w  = (const float*)d_in[2];
    const float* q_bias = (const float*)d_in[3];
    const float* v_bias = (const float*)d_in[4];
    const float* proj_w = (const float*)d_in[5];
    const float* proj_b = (const float*)d_in[6];
    const float* n1s    = (const float*)d_in[7];
    const float* n1b    = (const float*)d_in[8];
    const float* n2s    = (const float*)d_in[9];
    const float* n2b    = (const float*)d_in[10];
    const float* w1     = (const float*)d_in[11];
    const float* b1     = (const float*)d_in[12];
    const float* w2     = (const float*)d_in[13];
    const float* b2     = (const float*)d_in[14];
    const float* g1     = (const float*)d_in[15];
    const float* g2     = (const float*)d_in[16];
    float* out = (float*)d_out;

    __nv_bfloat16 *xn, *qkv, *vt, *attout, *h0, *h1, *w;
    float *x2, *maskf;
    cudaGetSymbolAddress((void**)&xn,     g_xn);
    cudaGetSymbolAddress((void**)&qkv,    g_qkv);
    cudaGetSymbolAddress((void**)&vt,     g_vt);
    cudaGetSymbolAddress((void**)&attout, g_attout);
    cudaGetSymbolAddress((void**)&h0,     g_h0);
    cudaGetSymbolAddress((void**)&h1,     g_h1);
    cudaGetSymbolAddress((void**)&w,      g_w);
    cudaGetSymbolAddress((void**)&x2,     g_x2);
    cudaGetSymbolAddress((void**)&maskf,  g_maskf);

    static int smem_set = 0;
    if (!smem_set) {
        cudaFuncSetAttribute(flash_kernel,
                             cudaFuncAttributeMaxDynamicSharedMemorySize, FLASH_SMEM);
        cudaFuncSetAttribute(mmgemm<EPI_QKV>,
                             cudaFuncAttributeMaxDynamicSharedMemorySize, GEMM_SMEM);
        cudaFuncSetAttribute(mmgemm<EPI_GELU>,
                             cudaFuncAttributeMaxDynamicSharedMemorySize, GEMM_SMEM);
        cudaFuncSetAttribute(mmgemm<EPI_RES>,
                             cudaFuncAttributeMaxDynamicSharedMemorySize, GEMM_SMEM);
        smem_set = 1;
    }

    // 0. convert all weights to bf16 in ONE launch
    round_copy_all_kernel<<<(NC_ALL + 255) / 256, 256>>>(
        qkv_w, proj_w, w1, w2, (unsigned*)w);

    // 1. LN1 + fused mask prep
    ln_kernel<<<NSEQ, 256>>>(x, n1s, n1b, xn);
    mask_fused_kernel<<<(NSEQ + 255) / 256, 256>>>(mask, maskf);

    // 2. QKV projection (882 tiles over 592 slots)
    mmgemm<EPI_QKV><<<dim3(49, C3 / 128, 1), 128, GEMM_SMEM>>>(
        xn, w + WQKV_OFF, qkv, NSEQ, C3, CD, CD, CD, C3,
        q_bias, v_bias, nullptr, nullptr, vt);

    // 3-5. flash attention (3-stage ring)
    flash_kernel<<<dim3(25, NH), 128, FLASH_SMEM>>>(qkv, vt, maskf, attout);

    // 6. proj + residual (294 tiles, single round)
    mmgemm<EPI_RES><<<dim3(49, CD / 128, 1), 128, GEMM_SMEM>>>(
        attout, w + WPROJ_OFF, x2, NSEQ, CD, CD, CD, CD, CD,
        proj_b, nullptr, x, g1, nullptr);

    // 7. LN2
    ln_kernel<<<NSEQ, 256>>>(x2, n2s, n2b, h0);

    // 8. MLP1 + exact GELU (1176 tiles = 1.99 rounds)
    mmgemm<EPI_GELU><<<dim3(49, HID / 128, 1), 128, GEMM_SMEM>>>(
        h0, w + W1_OFF, h1, NSEQ, HID, CD, CD, CD, HID,
        b1, nullptr, nullptr, nullptr, nullptr);

    // 9. MLP2 + final residual
    mmgemm<EPI_RES><<<dim3(49, CD / 128, 1), 128, GEMM_SMEM>>>(
        h1, w + W2_OFF, out, NSEQ, CD, HID, HID, HID, CD,
        b2, nullptr, x2, g2, nullptr);
}